// round 13
// baseline (speedup 1.0000x reference)
#include <cuda_runtime.h>
#include <cuda_fp16.h>
#include <cstdint>

#define NN 50000
#define NE 800000
#define NT256 3125            // 256-edge tiles

// ---------------- device scratch ----------------------------------------------
__device__ float d_agg[NN * 16];
__device__ float d_b3t[NN * 16];
__device__ float d_xt[NN * 16];
__device__ float d_asrc[NN];
__device__ float d_adst[NN];
__device__ unsigned int d_menc[NN];
__device__ float d_z[NN];
__device__ float d_gout[NN * 16];
// packed weight images (compact, conflict-free):
// B1F (1024 u32: {hi,lo} uint2/lane) | B2H (4096) | B3H (8192) | b2 (64)
__device__ unsigned d_wimg[13376];

// ---------------- helpers ------------------------------------------------------
__device__ __forceinline__ unsigned enc_f(float f) {
    unsigned u = __float_as_uint(f);
    return (u & 0x80000000u) ? ~u : (u | 0x80000000u);
}
__device__ __forceinline__ float dec_f(unsigned k) {
    return __uint_as_float((k & 0x80000000u) ? (k & 0x7fffffffu) : ~k);
}
__device__ __forceinline__ float lrelu(float v) { return v > 0.f ? v : 0.2f * v; }

__device__ __forceinline__ unsigned packh(float a, float b) {
    unsigned r;
    asm("cvt.rn.f16x2.f32 %0, %1, %2;" : "=r"(r) : "f"(b), "f"(a));
    return r;
}
__device__ __forceinline__ unsigned loh(unsigned hi, float a, float b) {
    float ha = __half2float(__ushort_as_half((unsigned short)(hi & 0xFFFFu)));
    float hb = __half2float(__ushort_as_half((unsigned short)(hi >> 16)));
    return packh(a - ha, b - hb);
}

__device__ __forceinline__ void mma16816(float* c, const unsigned* a,
                                         unsigned b0, unsigned b1) {
    asm volatile(
        "mma.sync.aligned.m16n8k16.row.col.f32.f16.f16.f32 "
        "{%0,%1,%2,%3}, {%4,%5,%6,%7}, {%8,%9}, {%0,%1,%2,%3};"
        : "+f"(c[0]), "+f"(c[1]), "+f"(c[2]), "+f"(c[3])
        : "r"(a[0]), "r"(a[1]), "r"(a[2]), "r"(a[3]), "r"(b0), "r"(b1));
}

// vector global reductions (sm_90+ baseline)
__device__ __forceinline__ void redv2(float* p, float a, float b) {
    asm volatile("red.global.add.v2.f32 [%0], {%1, %2};"
                 :: "l"(p), "f"(a), "f"(b) : "memory");
}
__device__ __forceinline__ void redv4(float* p, float a, float b, float c, float d) {
    asm volatile("red.global.add.v4.f32 [%0], {%1, %2, %3, %4};"
                 :: "l"(p), "f"(a), "f"(b), "f"(c), "f"(d) : "memory");
}

// smem byte offsets inside k2 (all 8B-aligned; lane stride 8B -> conflict-free)
#define SM_B1F 0
#define SM_B2H 4096
#define SM_B3H 20480
#define SM_B2B 53248
#define K2_SMEM 53504

// ---------------- K1: pack weights, compact conflict-free images ---------------
__global__ void k1_prep(const float* __restrict__ w1, const float* __restrict__ b1,
                        const float* __restrict__ w2, const float* __restrict__ w3,
                        const float* __restrict__ b2) {
    int t = blockIdx.x * blockDim.x + threadIdx.x;
    if (t >= 13376) return;
    if (t < 1024) {               // B1F
        int j = t & 1, e = t >> 1;
        int lane = e & 31, nt = e >> 5;
        int q = lane & 3, n = 8 * nt + (lane >> 2);
        float va = 0.f, vb = 0.f;
        if (q == 0) { va = w1[n]; vb = w1[128 + n]; }
        else if (q == 1) { va = w1[256 + n]; vb = b1[n]; }
        unsigned hi = packh(va, vb);
        d_wimg[t] = (q < 2) ? ((j == 0) ? hi : loh(hi, va, vb)) : 0u;
    } else if (t < 5120) {        // B2H from W2 [128,64]
        int u = t - 1024;
        int j = u & 1, e = u >> 1;
        int lane = e & 31, nt = (e >> 5) & 7, s = e >> 8;
        int kk = 16 * s + 2 * (lane & 3) + (j ? 8 : 0);
        int n = 8 * nt + (lane >> 2);
        d_wimg[t] = packh(w2[kk * 64 + n], w2[(kk + 1) * 64 + n]);
    } else if (t < 13312) {       // B3H from W3 [64,256]
        int u = t - 5120;
        int j = u & 1, e = u >> 1;
        int lane = e & 31, nt = (e >> 5) & 31, s3 = e >> 10;
        int kk = 16 * s3 + 2 * (lane & 3) + (j ? 8 : 0);
        int n = 8 * nt + (lane >> 2);
        d_wimg[t] = packh(w3[kk * 256 + n], w3[(kk + 1) * 256 + n]);
    } else {                      // b2
        d_wimg[t] = __float_as_uint(b2[t - 13312]);
    }
}

// ---------------- K0: agg init + b3 term + zero gout/z (4 threads / node) ------
__global__ void k0_root(const float* __restrict__ x, const float* __restrict__ rw,
                        const float* __restrict__ nb, const float* __restrict__ b3) {
    int gid = blockIdx.x * blockDim.x + threadIdx.x;
    if (gid >= NN * 4) return;
    int n = gid >> 2, ob = (gid & 3) * 4;
    float xr[16];
#pragma unroll
    for (int i = 0; i < 16; i += 4) {
        float4 v = __ldg((const float4*)&x[(size_t)n * 16 + i]);
        xr[i] = v.x; xr[i + 1] = v.y; xr[i + 2] = v.z; xr[i + 3] = v.w;
    }
    float av[4], bv[4];
#pragma unroll
    for (int oo = 0; oo < 4; oo++) {
        int o = ob + oo;
        float a = __ldg(&nb[o]);
        float b = 0.f;
#pragma unroll
        for (int i = 0; i < 16; i++) {
            a = fmaf(xr[i], __ldg(&rw[i * 16 + o]), a);
            b = fmaf(xr[i], __ldg(&b3[i * 16 + o]), b);
        }
        av[oo] = a; bv[oo] = b;
    }
    *(float4*)&d_agg[(size_t)n * 16 + ob] = make_float4(av[0], av[1], av[2], av[3]);
    *(float4*)&d_b3t[(size_t)n * 16 + ob] = make_float4(bv[0], bv[1], bv[2], bv[3]);
    *(float4*)&d_gout[(size_t)n * 16 + ob] = make_float4(0.f, 0.f, 0.f, 0.f);
    if ((gid & 3) == 0) d_z[n] = 0.f;
}

// ---------------- K2: fully tensorized edge pipeline ---------------------------
__global__ void __launch_bounds__(256, 2)
k2_edge(const float* __restrict__ x, const int* __restrict__ ei,
        const float* __restrict__ ea) {
    extern __shared__ unsigned char smc[];
    int tid = threadIdx.x;
    {
        const uint4* src = (const uint4*)d_wimg;
        uint4* dst = (uint4*)smc;
        for (int i = tid; i < 3344; i += 256) dst[i] = src[i];   // 13376 u32 = 3344 uint4
    }
    __syncthreads();

    const int w = tid >> 5, lane = tid & 31;
    const int q = lane & 3, l4 = lane >> 2;
    const int bq = 2 * q;
    const float* sb2 = (const float*)(smc + SM_B2B);

    for (int tile = blockIdx.x; tile < NT256; tile += gridDim.x) {
        const int base = (tile << 8) + (w << 5) + l4;   // rows base+{0,8,16,24}
        int srcv[4], dstv[4];
        unsigned eaf[2][2];                              // L1 A fragments
#pragma unroll
        for (int r = 0; r < 4; r += 2) {
            int e0 = base + 8 * r, e1 = e0 + 8;
            srcv[r] = __ldg(&ei[e0]);     srcv[r + 1] = __ldg(&ei[e1]);
            dstv[r] = __ldg(&ei[NE + e0]); dstv[r + 1] = __ldg(&ei[NE + e1]);
            float a0 = __ldg(&ea[(size_t)e0 * 3]);
            float a1 = __ldg(&ea[(size_t)e0 * 3 + 1]);
            float a2 = __ldg(&ea[(size_t)e0 * 3 + 2]);
            float b0 = __ldg(&ea[(size_t)e1 * 3]);
            float b1v = __ldg(&ea[(size_t)e1 * 3 + 1]);
            float b2v = __ldg(&ea[(size_t)e1 * 3 + 2]);
            int m = r >> 1;
            eaf[m][0] = (q == 0) ? packh(a0, a1) : ((q == 1) ? packh(a2, 1.0f) : 0u);
            eaf[m][1] = (q == 0) ? packh(b0, b1v) : ((q == 1) ? packh(b2v, 1.0f) : 0u);
        }

        // ---- L2 (with L1 on tensor cores): C2[m][16,64] ----
        float C2[2][8][4];
#pragma unroll
        for (int m = 0; m < 2; m++)
#pragma unroll
            for (int nt = 0; nt < 8; nt++)
#pragma unroll
                for (int v = 0; v < 4; v++) C2[m][nt][v] = 0.f;

#pragma unroll
        for (int s = 0; s < 8; s++) {
            // L1: C1 = ea @ W1 + b1 (exact W1 via hi in b0-slot, lo in b1-slot)
            float C1[2][2][4];
#pragma unroll
            for (int ntl = 0; ntl < 2; ntl++)
#pragma unroll
                for (int m = 0; m < 2; m++)
#pragma unroll
                    for (int v = 0; v < 4; v++) C1[ntl][m][v] = 0.f;
#pragma unroll
            for (int ntl = 0; ntl < 2; ntl++) {
                uint2 bw = *(const uint2*)(smc + SM_B1F + (((2 * s + ntl) * 32 + lane) << 3));
#pragma unroll
                for (int m = 0; m < 2; m++) {
                    unsigned a[4] = {eaf[m][0], eaf[m][1], eaf[m][0], eaf[m][1]};
                    mma16816(C1[ntl][m], a, bw.x, bw.y);
                }
            }
            // relu + pack -> L2 A fragments (C1 layout == A fragment layout)
            unsigned Ah[2][4];
#pragma unroll
            for (int m = 0; m < 2; m++) {
                Ah[m][0] = packh(fmaxf(C1[0][m][0], 0.f), fmaxf(C1[0][m][1], 0.f));
                Ah[m][1] = packh(fmaxf(C1[0][m][2], 0.f), fmaxf(C1[0][m][3], 0.f));
                Ah[m][2] = packh(fmaxf(C1[1][m][0], 0.f), fmaxf(C1[1][m][1], 0.f));
                Ah[m][3] = packh(fmaxf(C1[1][m][2], 0.f), fmaxf(C1[1][m][3], 0.f));
            }
#pragma unroll
            for (int nt = 0; nt < 8; nt++) {
                uint2 B = *(const uint2*)(smc + SM_B2H + (((s * 8 + nt) * 32 + lane) << 3));
#pragma unroll
                for (int m = 0; m < 2; m++)
                    mma16816(C2[m][nt], Ah[m], B.x, B.y);
            }
        }

        // ---- epilogue: +b2, relu -> A3 fragments ----
        unsigned A3h[2][4][4];
#pragma unroll
        for (int m = 0; m < 2; m++)
#pragma unroll
            for (int s3 = 0; s3 < 4; s3++) {
                int c = 16 * s3 + bq;
                float2 bA = *(const float2*)&sb2[c];
                float2 bB = *(const float2*)&sb2[c + 8];
                float v00 = fmaxf(C2[m][2 * s3][0] + bA.x, 0.f);
                float v01 = fmaxf(C2[m][2 * s3][1] + bA.y, 0.f);
                float v10 = fmaxf(C2[m][2 * s3][2] + bA.x, 0.f);
                float v11 = fmaxf(C2[m][2 * s3][3] + bA.y, 0.f);
                float v20 = fmaxf(C2[m][2 * s3 + 1][0] + bB.x, 0.f);
                float v21 = fmaxf(C2[m][2 * s3 + 1][1] + bB.y, 0.f);
                float v30 = fmaxf(C2[m][2 * s3 + 1][2] + bB.x, 0.f);
                float v31 = fmaxf(C2[m][2 * s3 + 1][3] + bB.y, 0.f);
                A3h[m][s3][0] = packh(v00, v01);
                A3h[m][s3][1] = packh(v10, v11);
                A3h[m][s3][2] = packh(v20, v21);
                A3h[m][s3][3] = packh(v30, v31);
            }

        // x[src] quarters (loaded after L2 to limit register pressure)
        float4 xq[4];
#pragma unroll
        for (int r = 0; r < 4; r++)
            xq[r] = *(const float4*)&x[(size_t)srcv[r] * 16 + 4 * q];

        // ---- L3 + einsum (weight-hi only) ----
        float macc[2][2][4];
#pragma unroll
        for (int m = 0; m < 2; m++)
#pragma unroll
            for (int r2 = 0; r2 < 2; r2++)
#pragma unroll
                for (int jj = 0; jj < 4; jj++) macc[m][r2][jj] = 0.f;

#pragma unroll
        for (int grp = 0; grp < 8; grp++) {
            float C3[2][4][4];
#pragma unroll
            for (int m = 0; m < 2; m++)
#pragma unroll
                for (int t = 0; t < 4; t++)
#pragma unroll
                    for (int v = 0; v < 4; v++) C3[m][t][v] = 0.f;
#pragma unroll
            for (int s3 = 0; s3 < 4; s3++) {
#pragma unroll
                for (int t = 0; t < 4; t++) {
                    int nt = grp * 4 + t;
                    uint2 B = *(const uint2*)(smc + SM_B3H + (((s3 * 32 + nt) * 32 + lane) << 3));
#pragma unroll
                    for (int m = 0; m < 2; m++)
                        mma16816(C3[m][t], A3h[m][s3], B.x, B.y);
                }
            }
#pragma unroll
            for (int t = 0; t < 4; t++) {
                const int nt = grp * 4 + t;
                const int i = nt >> 1;
                const int sl = (lane & ~3) | (i >> 2);
                float xv[4];
#pragma unroll
                for (int r = 0; r < 4; r++) {
                    float own;
                    switch (i & 3) {
                        case 0: own = xq[r].x; break;
                        case 1: own = xq[r].y; break;
                        case 2: own = xq[r].z; break;
                        default: own = xq[r].w; break;
                    }
                    xv[r] = __shfl_sync(0xffffffffu, own, sl);
                }
                const int p = nt & 1;
#pragma unroll
                for (int m = 0; m < 2; m++) {
                    macc[m][0][2 * p]     = fmaf(C3[m][t][0], xv[2 * m], macc[m][0][2 * p]);
                    macc[m][0][2 * p + 1] = fmaf(C3[m][t][1], xv[2 * m], macc[m][0][2 * p + 1]);
                    macc[m][1][2 * p]     = fmaf(C3[m][t][2], xv[2 * m + 1], macc[m][1][2 * p]);
                    macc[m][1][2 * p + 1] = fmaf(C3[m][t][3], xv[2 * m + 1], macc[m][1][2 * p + 1]);
                }
            }
        }

        // ---- flush: + b3t[src], vector-red into d_agg[dst] ----
#pragma unroll
        for (int m = 0; m < 2; m++)
#pragma unroll
            for (int r2 = 0; r2 < 2; r2++) {
                int r = 2 * m + r2;
                float2 pA = *(const float2*)&d_b3t[(size_t)srcv[r] * 16 + bq];
                float2 pB = *(const float2*)&d_b3t[(size_t)srcv[r] * 16 + bq + 8];
                float* a = &d_agg[(size_t)dstv[r] * 16];
                redv2(a + bq,     macc[m][r2][0] + pA.x, macc[m][r2][1] + pA.y);
                redv2(a + bq + 8, macc[m][r2][2] + pB.x, macc[m][r2][3] + pB.y);
            }
    }
}

// ---------------- K3: x1 = relu(agg); xt = x1@gat_w (4 threads / node) ---------
__global__ void k3_node(const float* __restrict__ gw, const float* __restrict__ as_,
                        const float* __restrict__ ad_) {
    __shared__ float sw[256], sa[16], sbv[16];
    int tid = threadIdx.x;
    if (tid < 256) sw[tid] = gw[tid];
    if (tid < 16) { sa[tid] = as_[tid]; sbv[tid] = ad_[tid]; }
    __syncthreads();
    int gid = blockIdx.x * blockDim.x + tid;
    if (gid >= NN * 4) return;
    int n = gid >> 2, ob = (gid & 3) * 4;
    float x1[16];
#pragma unroll
    for (int i = 0; i < 16; i++) x1[i] = fmaxf(d_agg[n * 16 + i], 0.f);
    float asrc = 0.f, adst = 0.f;
    float vo[4];
#pragma unroll
    for (int oo = 0; oo < 4; oo++) {
        int o = ob + oo;
        float v = 0.f;
#pragma unroll
        for (int i = 0; i < 16; i++) v = fmaf(x1[i], sw[i * 16 + o], v);
        vo[oo] = v;
        asrc = fmaf(v, sa[o], asrc);
        adst = fmaf(v, sbv[o], adst);
    }
    *(float4*)&d_xt[(size_t)n * 16 + ob] = make_float4(vo[0], vo[1], vo[2], vo[3]);
    asrc += __shfl_xor_sync(0xffffffffu, asrc, 1);
    adst += __shfl_xor_sync(0xffffffffu, adst, 1);
    asrc += __shfl_xor_sync(0xffffffffu, asrc, 2);
    adst += __shfl_xor_sync(0xffffffffu, adst, 2);
    if ((gid & 3) == 0) {
        d_asrc[n] = asrc;
        d_adst[n] = adst;
        d_menc[n] = enc_f(lrelu(asrc + adst));   // self-loop seeds the max
    }
}

// ---------------- K4: segment max (2 edges / thread, no logit store) -----------
__global__ void k4_edge(const int* __restrict__ ei) {
    int t = blockIdx.x * blockDim.x + threadIdx.x;
    if (t >= NE / 2) return;
    int2 s2 = __ldg(&((const int2*)ei)[t]);
    int2 d2 = __ldg(&((const int2*)(ei + NE))[t]);
    atomicMax(&d_menc[d2.x], enc_f(lrelu(d_asrc[s2.x] + d_adst[d2.x])));
    atomicMax(&d_menc[d2.y], enc_f(lrelu(d_asrc[s2.y] + d_adst[d2.y])));
}

// ---------------- K6: softmax-weighted scatter (4 threads / edge, red.v4) ------
// e recomputed from asrc/adst (bitwise identical to k4's value; both L2-resident)
__global__ void k6_edge(const int* __restrict__ ei) {
    int gid = blockIdx.x * blockDim.x + threadIdx.x;
    if (gid >= NE * 4) return;
    int e = gid >> 2, part = gid & 3;
    int s = ei[e], d = ei[NE + e];
    float wv = __expf(lrelu(d_asrc[s] + d_adst[d]) - dec_f(d_menc[d]));
    float4 xv = *(const float4*)&d_xt[(size_t)s * 16 + part * 4];
    redv4(&d_gout[(size_t)d * 16 + part * 4],
          wv * xv.x, wv * xv.y, wv * xv.z, wv * xv.w);
    if (part == 0) atomicAdd(&d_z[d], wv);
}

// ---------------- K7: self-loop fold + normalize + fc1 (4 thr / node) ----------
__global__ void k7_node(const float* __restrict__ fw, const float* __restrict__ fb,
                        const float* __restrict__ gb, float* __restrict__ out) {
    __shared__ float sw[1024], sbv[64], sgb[16];
    int tid = threadIdx.x;
    for (int i = tid; i < 1024; i += blockDim.x) sw[i] = fw[i];
    if (tid < 64) sbv[tid] = fb[tid];
    if (tid < 16) sgb[tid] = gb[tid];
    __syncthreads();
    int gid = blockIdx.x * blockDim.x + tid;
    if (gid >= NN * 4) return;
    int n = gid >> 2, jb = (gid & 3) * 16;
    float m = dec_f(d_menc[n]);
    float wself = __expf(lrelu(d_asrc[n] + d_adst[n]) - m);
    float inv = 1.f / (d_z[n] + wself);
    float x2[16];
#pragma unroll
    for (int i = 0; i < 16; i++) {
        float g = d_gout[n * 16 + i] + wself * d_xt[n * 16 + i];
        x2[i] = fmaxf(g * inv + sgb[i], 0.f);
    }
#pragma unroll 4
    for (int jj = 0; jj < 16; jj++) {
        int j = jb + jj;
        float a = sbv[j];
#pragma unroll
        for (int i = 0; i < 16; i++) a = fmaf(x2[i], sw[i * 64 + j], a);
        out[(size_t)n * 64 + j] = fmaxf(a, 0.f);
    }
}

// ---------------- launch -------------------------------------------------------
extern "C" void kernel_launch(void* const* d_in, const int* in_sizes, int n_in,
                              void* d_out, int out_size) {
    const float* x = (const float*)d_in[0];
    const int* ei = (const int*)d_in[1];
    const float* ea = (const float*)d_in[2];
    const float* w1 = (const float*)d_in[4];
    const float* b1 = (const float*)d_in[5];
    const float* w2 = (const float*)d_in[6];
    const float* b2 = (const float*)d_in[7];
    const float* w3 = (const float*)d_in[8];
    const float* b3 = (const float*)d_in[9];
    const float* rootw = (const float*)d_in[10];
    const float* nnb = (const float*)d_in[11];
    const float* gatw = (const float*)d_in[12];
    const float* atts = (const float*)d_in[13];
    const float* attd = (const float*)d_in[14];
    const float* gatb = (const float*)d_in[15];
    const float* fc1w = (const float*)d_in[16];
    const float* fc1b = (const float*)d_in[17];
    float* out = (float*)d_out;

    cudaFuncSetAttribute(k2_edge, cudaFuncAttributeMaxDynamicSharedMemorySize, K2_SMEM);

    k1_prep<<<(13376 + 255) / 256, 256>>>(w1, b1, w2, w3, b2);
    k0_root<<<(NN * 4 + 255) / 256, 256>>>(x, rootw, nnb, b3);
    k2_edge<<<296, 256, K2_SMEM>>>(x, ei, ea);
    k3_node<<<(NN * 4 + 255) / 256, 256>>>(gatw, atts, attd);
    k4_edge<<<(NE / 2 + 255) / 256, 256>>>(ei);
    k6_edge<<<(NE * 4 + 255) / 256, 256>>>(ei);
    k7_node<<<(NN * 4 + 255) / 256, 256>>>(fc1w, fc1b, gatb, out);
}

// round 14
// speedup vs baseline: 1.0181x; 1.0181x over previous
#include <cuda_runtime.h>
#include <cuda_fp16.h>
#include <cstdint>

#define NN 50000
#define NE 800000
#define NT256 3125            // 256-edge tiles

// ---------------- device scratch ----------------------------------------------
__device__ float d_agg[NN * 16];
__device__ float d_b3t[NN * 16];
__device__ float d_xt[NN * 16];
__device__ float d_asrc[NN];
__device__ float d_adst[NN];
__device__ unsigned int d_menc[NN];
__device__ float d_z[NN];
__device__ float d_gout[NN * 16];
__device__ float d_ebuf[NE];
// packed weight images (compact, conflict-free):
// B1F (1024 u32: {hi,lo} uint2/lane) | B2H (4096) | B3H (8192) | b2 (64)
__device__ unsigned d_wimg[13376];

// ---------------- helpers ------------------------------------------------------
__device__ __forceinline__ unsigned enc_f(float f) {
    unsigned u = __float_as_uint(f);
    return (u & 0x80000000u) ? ~u : (u | 0x80000000u);
}
__device__ __forceinline__ float dec_f(unsigned k) {
    return __uint_as_float((k & 0x80000000u) ? (k & 0x7fffffffu) : ~k);
}
__device__ __forceinline__ float lrelu(float v) { return v > 0.f ? v : 0.2f * v; }

__device__ __forceinline__ unsigned packh(float a, float b) {
    unsigned r;
    asm("cvt.rn.f16x2.f32 %0, %1, %2;" : "=r"(r) : "f"(b), "f"(a));
    return r;
}
__device__ __forceinline__ unsigned loh(unsigned hi, float a, float b) {
    float ha = __half2float(__ushort_as_half((unsigned short)(hi & 0xFFFFu)));
    float hb = __half2float(__ushort_as_half((unsigned short)(hi >> 16)));
    return packh(a - ha, b - hb);
}

__device__ __forceinline__ void mma16816(float* c, const unsigned* a,
                                         unsigned b0, unsigned b1) {
    asm volatile(
        "mma.sync.aligned.m16n8k16.row.col.f32.f16.f16.f32 "
        "{%0,%1,%2,%3}, {%4,%5,%6,%7}, {%8,%9}, {%0,%1,%2,%3};"
        : "+f"(c[0]), "+f"(c[1]), "+f"(c[2]), "+f"(c[3])
        : "r"(a[0]), "r"(a[1]), "r"(a[2]), "r"(a[3]), "r"(b0), "r"(b1));
}

// vector global reductions (sm_90+ baseline)
__device__ __forceinline__ void redv2(float* p, float a, float b) {
    asm volatile("red.global.add.v2.f32 [%0], {%1, %2};"
                 :: "l"(p), "f"(a), "f"(b) : "memory");
}
__device__ __forceinline__ void redv4(float* p, float a, float b, float c, float d) {
    asm volatile("red.global.add.v4.f32 [%0], {%1, %2, %3, %4};"
                 :: "l"(p), "f"(a), "f"(b), "f"(c), "f"(d) : "memory");
}

// smem byte offsets inside k2 (all 8B-aligned; lane stride 8B -> conflict-free)
#define SM_B1F 0
#define SM_B2H 4096
#define SM_B3H 20480
#define SM_B2B 53248
#define K2_SMEM 53504

// ---------------- K1: pack weights, compact conflict-free images ---------------
__global__ void k1_prep(const float* __restrict__ w1, const float* __restrict__ b1,
                        const float* __restrict__ w2, const float* __restrict__ w3,
                        const float* __restrict__ b2) {
    int t = blockIdx.x * blockDim.x + threadIdx.x;
    if (t >= 13376) return;
    if (t < 1024) {               // B1F
        int j = t & 1, e = t >> 1;
        int lane = e & 31, nt = e >> 5;
        int q = lane & 3, n = 8 * nt + (lane >> 2);
        float va = 0.f, vb = 0.f;
        if (q == 0) { va = w1[n]; vb = w1[128 + n]; }
        else if (q == 1) { va = w1[256 + n]; vb = b1[n]; }
        unsigned hi = packh(va, vb);
        d_wimg[t] = (q < 2) ? ((j == 0) ? hi : loh(hi, va, vb)) : 0u;
    } else if (t < 5120) {        // B2H from W2 [128,64]
        int u = t - 1024;
        int j = u & 1, e = u >> 1;
        int lane = e & 31, nt = (e >> 5) & 7, s = e >> 8;
        int kk = 16 * s + 2 * (lane & 3) + (j ? 8 : 0);
        int n = 8 * nt + (lane >> 2);
        d_wimg[t] = packh(w2[kk * 64 + n], w2[(kk + 1) * 64 + n]);
    } else if (t < 13312) {       // B3H from W3 [64,256]
        int u = t - 5120;
        int j = u & 1, e = u >> 1;
        int lane = e & 31, nt = (e >> 5) & 31, s3 = e >> 10;
        int kk = 16 * s3 + 2 * (lane & 3) + (j ? 8 : 0);
        int n = 8 * nt + (lane >> 2);
        d_wimg[t] = packh(w3[kk * 256 + n], w3[(kk + 1) * 256 + n]);
    } else {                      // b2
        d_wimg[t] = __float_as_uint(b2[t - 13312]);
    }
}

// ---------------- K0: agg init + b3 term + zero gout/z (4 threads / node) ------
__global__ void k0_root(const float* __restrict__ x, const float* __restrict__ rw,
                        const float* __restrict__ nb, const float* __restrict__ b3) {
    int gid = blockIdx.x * blockDim.x + threadIdx.x;
    if (gid >= NN * 4) return;
    int n = gid >> 2, ob = (gid & 3) * 4;
    float xr[16];
#pragma unroll
    for (int i = 0; i < 16; i += 4) {
        float4 v = __ldg((const float4*)&x[(size_t)n * 16 + i]);
        xr[i] = v.x; xr[i + 1] = v.y; xr[i + 2] = v.z; xr[i + 3] = v.w;
    }
    float av[4], bv[4];
#pragma unroll
    for (int oo = 0; oo < 4; oo++) {
        int o = ob + oo;
        float a = __ldg(&nb[o]);
        float b = 0.f;
#pragma unroll
        for (int i = 0; i < 16; i++) {
            a = fmaf(xr[i], __ldg(&rw[i * 16 + o]), a);
            b = fmaf(xr[i], __ldg(&b3[i * 16 + o]), b);
        }
        av[oo] = a; bv[oo] = b;
    }
    *(float4*)&d_agg[(size_t)n * 16 + ob] = make_float4(av[0], av[1], av[2], av[3]);
    *(float4*)&d_b3t[(size_t)n * 16 + ob] = make_float4(bv[0], bv[1], bv[2], bv[3]);
    *(float4*)&d_gout[(size_t)n * 16 + ob] = make_float4(0.f, 0.f, 0.f, 0.f);
    if ((gid & 3) == 0) d_z[n] = 0.f;
}

// ---------------- K2: fully tensorized edge pipeline ---------------------------
__global__ void __launch_bounds__(256, 2)
k2_edge(const float* __restrict__ x, const int* __restrict__ ei,
        const float* __restrict__ ea) {
    extern __shared__ unsigned char smc[];
    int tid = threadIdx.x;
    {
        const uint4* src = (const uint4*)d_wimg;
        uint4* dst = (uint4*)smc;
        for (int i = tid; i < 3344; i += 256) dst[i] = src[i];   // 13376 u32 = 3344 uint4
    }
    __syncthreads();

    const int w = tid >> 5, lane = tid & 31;
    const int q = lane & 3, l4 = lane >> 2;
    const int bq = 2 * q;
    const float* sb2 = (const float*)(smc + SM_B2B);

    for (int tile = blockIdx.x; tile < NT256; tile += gridDim.x) {
        const int base = (tile << 8) + (w << 5) + l4;   // rows base+{0,8,16,24}
        int srcv[4], dstv[4];
        unsigned eaf[2][2];                              // L1 A fragments
#pragma unroll
        for (int r = 0; r < 4; r += 2) {
            int e0 = base + 8 * r, e1 = e0 + 8;
            srcv[r] = __ldg(&ei[e0]);     srcv[r + 1] = __ldg(&ei[e1]);
            dstv[r] = __ldg(&ei[NE + e0]); dstv[r + 1] = __ldg(&ei[NE + e1]);
            float a0 = __ldg(&ea[(size_t)e0 * 3]);
            float a1 = __ldg(&ea[(size_t)e0 * 3 + 1]);
            float a2 = __ldg(&ea[(size_t)e0 * 3 + 2]);
            float b0 = __ldg(&ea[(size_t)e1 * 3]);
            float b1v = __ldg(&ea[(size_t)e1 * 3 + 1]);
            float b2v = __ldg(&ea[(size_t)e1 * 3 + 2]);
            int m = r >> 1;
            eaf[m][0] = (q == 0) ? packh(a0, a1) : ((q == 1) ? packh(a2, 1.0f) : 0u);
            eaf[m][1] = (q == 0) ? packh(b0, b1v) : ((q == 1) ? packh(b2v, 1.0f) : 0u);
        }

        // ---- L2 (with L1 on tensor cores): C2[m][16,64] ----
        float C2[2][8][4];
#pragma unroll
        for (int m = 0; m < 2; m++)
#pragma unroll
            for (int nt = 0; nt < 8; nt++)
#pragma unroll
                for (int v = 0; v < 4; v++) C2[m][nt][v] = 0.f;

#pragma unroll
        for (int s = 0; s < 8; s++) {
            // L1: C1 = ea @ W1 + b1 (exact W1 via hi in b0-slot, lo in b1-slot)
            float C1[2][2][4];
#pragma unroll
            for (int ntl = 0; ntl < 2; ntl++)
#pragma unroll
                for (int m = 0; m < 2; m++)
#pragma unroll
                    for (int v = 0; v < 4; v++) C1[ntl][m][v] = 0.f;
#pragma unroll
            for (int ntl = 0; ntl < 2; ntl++) {
                uint2 bw = *(const uint2*)(smc + SM_B1F + (((2 * s + ntl) * 32 + lane) << 3));
#pragma unroll
                for (int m = 0; m < 2; m++) {
                    unsigned a[4] = {eaf[m][0], eaf[m][1], eaf[m][0], eaf[m][1]};
                    mma16816(C1[ntl][m], a, bw.x, bw.y);
                }
            }
            // relu + pack -> L2 A fragments (C1 layout == A fragment layout)
            unsigned Ah[2][4];
#pragma unroll
            for (int m = 0; m < 2; m++) {
                Ah[m][0] = packh(fmaxf(C1[0][m][0], 0.f), fmaxf(C1[0][m][1], 0.f));
                Ah[m][1] = packh(fmaxf(C1[0][m][2], 0.f), fmaxf(C1[0][m][3], 0.f));
                Ah[m][2] = packh(fmaxf(C1[1][m][0], 0.f), fmaxf(C1[1][m][1], 0.f));
                Ah[m][3] = packh(fmaxf(C1[1][m][2], 0.f), fmaxf(C1[1][m][3], 0.f));
            }
#pragma unroll
            for (int nt = 0; nt < 8; nt++) {
                uint2 B = *(const uint2*)(smc + SM_B2H + (((s * 8 + nt) * 32 + lane) << 3));
#pragma unroll
                for (int m = 0; m < 2; m++)
                    mma16816(C2[m][nt], Ah[m], B.x, B.y);
            }
        }

        // ---- epilogue: +b2, relu -> A3 fragments ----
        unsigned A3h[2][4][4];
#pragma unroll
        for (int m = 0; m < 2; m++)
#pragma unroll
            for (int s3 = 0; s3 < 4; s3++) {
                int c = 16 * s3 + bq;
                float2 bA = *(const float2*)&sb2[c];
                float2 bB = *(const float2*)&sb2[c + 8];
                float v00 = fmaxf(C2[m][2 * s3][0] + bA.x, 0.f);
                float v01 = fmaxf(C2[m][2 * s3][1] + bA.y, 0.f);
                float v10 = fmaxf(C2[m][2 * s3][2] + bA.x, 0.f);
                float v11 = fmaxf(C2[m][2 * s3][3] + bA.y, 0.f);
                float v20 = fmaxf(C2[m][2 * s3 + 1][0] + bB.x, 0.f);
                float v21 = fmaxf(C2[m][2 * s3 + 1][1] + bB.y, 0.f);
                float v30 = fmaxf(C2[m][2 * s3 + 1][2] + bB.x, 0.f);
                float v31 = fmaxf(C2[m][2 * s3 + 1][3] + bB.y, 0.f);
                A3h[m][s3][0] = packh(v00, v01);
                A3h[m][s3][1] = packh(v10, v11);
                A3h[m][s3][2] = packh(v20, v21);
                A3h[m][s3][3] = packh(v30, v31);
            }

        // x[src] quarters (loaded after L2 to limit register pressure)
        float4 xq[4];
#pragma unroll
        for (int r = 0; r < 4; r++)
            xq[r] = *(const float4*)&x[(size_t)srcv[r] * 16 + 4 * q];

        // ---- L3 + einsum (weight-hi only) ----
        float macc[2][2][4];
#pragma unroll
        for (int m = 0; m < 2; m++)
#pragma unroll
            for (int r2 = 0; r2 < 2; r2++)
#pragma unroll
                for (int jj = 0; jj < 4; jj++) macc[m][r2][jj] = 0.f;

#pragma unroll
        for (int grp = 0; grp < 8; grp++) {
            float C3[2][4][4];
#pragma unroll
            for (int m = 0; m < 2; m++)
#pragma unroll
                for (int t = 0; t < 4; t++)
#pragma unroll
                    for (int v = 0; v < 4; v++) C3[m][t][v] = 0.f;
#pragma unroll
            for (int s3 = 0; s3 < 4; s3++) {
#pragma unroll
                for (int t = 0; t < 4; t++) {
                    int nt = grp * 4 + t;
                    uint2 B = *(const uint2*)(smc + SM_B3H + (((s3 * 32 + nt) * 32 + lane) << 3));
#pragma unroll
                    for (int m = 0; m < 2; m++)
                        mma16816(C3[m][t], A3h[m][s3], B.x, B.y);
                }
            }
#pragma unroll
            for (int t = 0; t < 4; t++) {
                const int nt = grp * 4 + t;
                const int i = nt >> 1;
                const int sl = (lane & ~3) | (i >> 2);
                float xv[4];
#pragma unroll
                for (int r = 0; r < 4; r++) {
                    float own;
                    switch (i & 3) {
                        case 0: own = xq[r].x; break;
                        case 1: own = xq[r].y; break;
                        case 2: own = xq[r].z; break;
                        default: own = xq[r].w; break;
                    }
                    xv[r] = __shfl_sync(0xffffffffu, own, sl);
                }
                const int p = nt & 1;
#pragma unroll
                for (int m = 0; m < 2; m++) {
                    macc[m][0][2 * p]     = fmaf(C3[m][t][0], xv[2 * m], macc[m][0][2 * p]);
                    macc[m][0][2 * p + 1] = fmaf(C3[m][t][1], xv[2 * m], macc[m][0][2 * p + 1]);
                    macc[m][1][2 * p]     = fmaf(C3[m][t][2], xv[2 * m + 1], macc[m][1][2 * p]);
                    macc[m][1][2 * p + 1] = fmaf(C3[m][t][3], xv[2 * m + 1], macc[m][1][2 * p + 1]);
                }
            }
        }

        // ---- flush: + b3t[src], vector-red into d_agg[dst] ----
#pragma unroll
        for (int m = 0; m < 2; m++)
#pragma unroll
            for (int r2 = 0; r2 < 2; r2++) {
                int r = 2 * m + r2;
                float2 pA = *(const float2*)&d_b3t[(size_t)srcv[r] * 16 + bq];
                float2 pB = *(const float2*)&d_b3t[(size_t)srcv[r] * 16 + bq + 8];
                float* a = &d_agg[(size_t)dstv[r] * 16];
                redv2(a + bq,     macc[m][r2][0] + pA.x, macc[m][r2][1] + pA.y);
                redv2(a + bq + 8, macc[m][r2][2] + pB.x, macc[m][r2][3] + pB.y);
            }
    }
}

// ---------------- K3: x1 = relu(agg); xt = x1@gat_w (4 threads / node) ---------
__global__ void k3_node(const float* __restrict__ gw, const float* __restrict__ as_,
                        const float* __restrict__ ad_) {
    __shared__ float sw[256], sa[16], sbv[16];
    int tid = threadIdx.x;
    if (tid < 256) sw[tid] = gw[tid];
    if (tid < 16) { sa[tid] = as_[tid]; sbv[tid] = ad_[tid]; }
    __syncthreads();
    int gid = blockIdx.x * blockDim.x + tid;
    if (gid >= NN * 4) return;
    int n = gid >> 2, ob = (gid & 3) * 4;
    float x1[16];
#pragma unroll
    for (int i = 0; i < 16; i++) x1[i] = fmaxf(d_agg[n * 16 + i], 0.f);
    float asrc = 0.f, adst = 0.f;
    float vo[4];
#pragma unroll
    for (int oo = 0; oo < 4; oo++) {
        int o = ob + oo;
        float v = 0.f;
#pragma unroll
        for (int i = 0; i < 16; i++) v = fmaf(x1[i], sw[i * 16 + o], v);
        vo[oo] = v;
        asrc = fmaf(v, sa[o], asrc);
        adst = fmaf(v, sbv[o], adst);
    }
    *(float4*)&d_xt[(size_t)n * 16 + ob] = make_float4(vo[0], vo[1], vo[2], vo[3]);
    asrc += __shfl_xor_sync(0xffffffffu, asrc, 1);
    adst += __shfl_xor_sync(0xffffffffu, adst, 1);
    asrc += __shfl_xor_sync(0xffffffffu, asrc, 2);
    adst += __shfl_xor_sync(0xffffffffu, adst, 2);
    if ((gid & 3) == 0) {
        d_asrc[n] = asrc;
        d_adst[n] = adst;
        d_menc[n] = enc_f(lrelu(asrc + adst));   // self-loop seeds the max
    }
}

// ---------------- K4: edge logits + segment max (2 edges / thread) -------------
__global__ void k4_edge(const int* __restrict__ ei) {
    int t = blockIdx.x * blockDim.x + threadIdx.x;
    if (t >= NE / 2) return;
    int2 s2 = __ldg(&((const int2*)ei)[t]);
    int2 d2 = __ldg(&((const int2*)(ei + NE))[t]);
    float v0 = lrelu(d_asrc[s2.x] + d_adst[d2.x]);
    float v1 = lrelu(d_asrc[s2.y] + d_adst[d2.y]);
    *(float2*)&d_ebuf[2 * t] = make_float2(v0, v1);
    atomicMax(&d_menc[d2.x], enc_f(v0));
    atomicMax(&d_menc[d2.y], enc_f(v1));
}

// ---------------- K6: softmax-weighted scatter (4 threads / edge, red.v4) ------
__global__ void k6_edge(const int* __restrict__ ei) {
    int gid = blockIdx.x * blockDim.x + threadIdx.x;
    if (gid >= NE * 4) return;
    int e = gid >> 2, part = gid & 3;
    int s = ei[e], d = ei[NE + e];
    float wv = __expf(d_ebuf[e] - dec_f(d_menc[d]));
    float4 xv = *(const float4*)&d_xt[(size_t)s * 16 + part * 4];
    redv4(&d_gout[(size_t)d * 16 + part * 4],
          wv * xv.x, wv * xv.y, wv * xv.z, wv * xv.w);
    if (part == 0) atomicAdd(&d_z[d], wv);
}

// ---------------- K7: self-loop fold + normalize + fc1 (4 thr / node) ----------
__global__ void k7_node(const float* __restrict__ fw, const float* __restrict__ fb,
                        const float* __restrict__ gb, float* __restrict__ out) {
    __shared__ float sw[1024], sbv[64], sgb[16];
    int tid = threadIdx.x;
    for (int i = tid; i < 1024; i += blockDim.x) sw[i] = fw[i];
    if (tid < 64) sbv[tid] = fb[tid];
    if (tid < 16) sgb[tid] = gb[tid];
    __syncthreads();
    int gid = blockIdx.x * blockDim.x + tid;
    if (gid >= NN * 4) return;
    int n = gid >> 2, jb = (gid & 3) * 16;
    float m = dec_f(d_menc[n]);
    float wself = __expf(lrelu(d_asrc[n] + d_adst[n]) - m);
    float inv = 1.f / (d_z[n] + wself);
    float x2[16];
#pragma unroll
    for (int i = 0; i < 16; i++) {
        float g = d_gout[n * 16 + i] + wself * d_xt[n * 16 + i];
        x2[i] = fmaxf(g * inv + sgb[i], 0.f);
    }
#pragma unroll 4
    for (int jj = 0; jj < 16; jj++) {
        int j = jb + jj;
        float a = sbv[j];
#pragma unroll
        for (int i = 0; i < 16; i++) a = fmaf(x2[i], sw[i * 64 + j], a);
        out[(size_t)n * 64 + j] = fmaxf(a, 0.f);
    }
}

// ---------------- launch -------------------------------------------------------
extern "C" void kernel_launch(void* const* d_in, const int* in_sizes, int n_in,
                              void* d_out, int out_size) {
    const float* x = (const float*)d_in[0];
    const int* ei = (const int*)d_in[1];
    const float* ea = (const float*)d_in[2];
    const float* w1 = (const float*)d_in[4];
    const float* b1 = (const float*)d_in[5];
    const float* w2 = (const float*)d_in[6];
    const float* b2 = (const float*)d_in[7];
    const float* w3 = (const float*)d_in[8];
    const float* b3 = (const float*)d_in[9];
    const float* rootw = (const float*)d_in[10];
    const float* nnb = (const float*)d_in[11];
    const float* gatw = (const float*)d_in[12];
    const float* atts = (const float*)d_in[13];
    const float* attd = (const float*)d_in[14];
    const float* gatb = (const float*)d_in[15];
    const float* fc1w = (const float*)d_in[16];
    const float* fc1b = (const float*)d_in[17];
    float* out = (float*)d_out;

    cudaFuncSetAttribute(k2_edge, cudaFuncAttributeMaxDynamicSharedMemorySize, K2_SMEM);

    k1_prep<<<(13376 + 255) / 256, 256>>>(w1, b1, w2, w3, b2);
    k0_root<<<(NN * 4 + 255) / 256, 256>>>(x, rootw, nnb, b3);
    k2_edge<<<296, 256, K2_SMEM>>>(x, ei, ea);
    k3_node<<<(NN * 4 + 255) / 256, 256>>>(gatw, atts, attd);
    k4_edge<<<(NE / 2 + 255) / 256, 256>>>(ei);
    k6_edge<<<(NE * 4 + 255) / 256, 256>>>(ei);
    k7_node<<<(NN * 4 + 255) / 256, 256>>>(fc1w, fc1b, gatb, out);
}

// round 15
// speedup vs baseline: 1.0522x; 1.0336x over previous
#include <cuda_runtime.h>
#include <cuda_fp16.h>
#include <cstdint>

#define NN 50000
#define NE 800000
#define NT256 3125            // 256-edge tiles
#define NB_K0 782             // ceil(NN*4/256)
#define NB_K1 53              // ceil(13376/256)

// ---------------- device scratch ----------------------------------------------
__device__ float d_agg[NN * 16];
__device__ float d_b3t[NN * 16];
__device__ float d_xt[NN * 16];
__device__ float d_asrc[NN];
__device__ float d_adst[NN];
__device__ unsigned int d_menc[NN];
__device__ float d_z[NN];
__device__ float d_gout[NN * 16];
__device__ float d_ebuf[NE];
// packed weight images (compact, conflict-free):
// B1F (1024 u32: {hi,lo} uint2/lane) | B2H (4096) | B3H (8192) | b2 (64)
__device__ unsigned d_wimg[13376];

// ---------------- helpers ------------------------------------------------------
__device__ __forceinline__ unsigned enc_f(float f) {
    unsigned u = __float_as_uint(f);
    return (u & 0x80000000u) ? ~u : (u | 0x80000000u);
}
__device__ __forceinline__ float dec_f(unsigned k) {
    return __uint_as_float((k & 0x80000000u) ? (k & 0x7fffffffu) : ~k);
}
__device__ __forceinline__ float lrelu(float v) { return v > 0.f ? v : 0.2f * v; }

__device__ __forceinline__ unsigned packh(float a, float b) {
    unsigned r;
    asm("cvt.rn.f16x2.f32 %0, %1, %2;" : "=r"(r) : "f"(b), "f"(a));
    return r;
}
__device__ __forceinline__ unsigned loh(unsigned hi, float a, float b) {
    float ha = __half2float(__ushort_as_half((unsigned short)(hi & 0xFFFFu)));
    float hb = __half2float(__ushort_as_half((unsigned short)(hi >> 16)));
    return packh(a - ha, b - hb);
}

__device__ __forceinline__ void mma16816(float* c, const unsigned* a,
                                         unsigned b0, unsigned b1) {
    asm volatile(
        "mma.sync.aligned.m16n8k16.row.col.f32.f16.f16.f32 "
        "{%0,%1,%2,%3}, {%4,%5,%6,%7}, {%8,%9}, {%0,%1,%2,%3};"
        : "+f"(c[0]), "+f"(c[1]), "+f"(c[2]), "+f"(c[3])
        : "r"(a[0]), "r"(a[1]), "r"(a[2]), "r"(a[3]), "r"(b0), "r"(b1));
}

// vector global reductions (sm_90+ baseline)
__device__ __forceinline__ void redv2(float* p, float a, float b) {
    asm volatile("red.global.add.v2.f32 [%0], {%1, %2};"
                 :: "l"(p), "f"(a), "f"(b) : "memory");
}
__device__ __forceinline__ void redv4(float* p, float a, float b, float c, float d) {
    asm volatile("red.global.add.v4.f32 [%0], {%1, %2, %3, %4};"
                 :: "l"(p), "f"(a), "f"(b), "f"(c), "f"(d) : "memory");
}

// smem byte offsets inside k2 (all 8B-aligned; lane stride 8B -> conflict-free)
#define SM_B1F 0
#define SM_B2H 4096
#define SM_B3H 20480
#define SM_B2B 53248
#define K2_SMEM 53504

// ---------------- K0: fused prep — node init (blocks < NB_K0) + weight pack ----
__global__ void k0_fused(const float* __restrict__ x, const float* __restrict__ rw,
                         const float* __restrict__ nb, const float* __restrict__ b3,
                         const float* __restrict__ w1, const float* __restrict__ b1,
                         const float* __restrict__ w2, const float* __restrict__ w3,
                         const float* __restrict__ b2) {
    if (blockIdx.x < NB_K0) {
        int gid = blockIdx.x * blockDim.x + threadIdx.x;
        if (gid >= NN * 4) return;
        int n = gid >> 2, ob = (gid & 3) * 4;
        float xr[16];
#pragma unroll
        for (int i = 0; i < 16; i += 4) {
            float4 v = __ldg((const float4*)&x[(size_t)n * 16 + i]);
            xr[i] = v.x; xr[i + 1] = v.y; xr[i + 2] = v.z; xr[i + 3] = v.w;
        }
        float av[4], bv[4];
#pragma unroll
        for (int oo = 0; oo < 4; oo++) {
            int o = ob + oo;
            float a = __ldg(&nb[o]);
            float b = 0.f;
#pragma unroll
            for (int i = 0; i < 16; i++) {
                a = fmaf(xr[i], __ldg(&rw[i * 16 + o]), a);
                b = fmaf(xr[i], __ldg(&b3[i * 16 + o]), b);
            }
            av[oo] = a; bv[oo] = b;
        }
        *(float4*)&d_agg[(size_t)n * 16 + ob] = make_float4(av[0], av[1], av[2], av[3]);
        *(float4*)&d_b3t[(size_t)n * 16 + ob] = make_float4(bv[0], bv[1], bv[2], bv[3]);
        *(float4*)&d_gout[(size_t)n * 16 + ob] = make_float4(0.f, 0.f, 0.f, 0.f);
        if ((gid & 3) == 0) d_z[n] = 0.f;
        return;
    }
    // ---- weight pack path ----
    int t = (blockIdx.x - NB_K0) * blockDim.x + threadIdx.x;
    if (t >= 13376) return;
    if (t < 1024) {               // B1F
        int j = t & 1, e = t >> 1;
        int lane = e & 31, nt = e >> 5;
        int q = lane & 3, n = 8 * nt + (lane >> 2);
        float va = 0.f, vb = 0.f;
        if (q == 0) { va = w1[n]; vb = w1[128 + n]; }
        else if (q == 1) { va = w1[256 + n]; vb = b1[n]; }
        unsigned hi = packh(va, vb);
        d_wimg[t] = (q < 2) ? ((j == 0) ? hi : loh(hi, va, vb)) : 0u;
    } else if (t < 5120) {        // B2H from W2 [128,64]
        int u = t - 1024;
        int j = u & 1, e = u >> 1;
        int lane = e & 31, nt = (e >> 5) & 7, s = e >> 8;
        int kk = 16 * s + 2 * (lane & 3) + (j ? 8 : 0);
        int n = 8 * nt + (lane >> 2);
        d_wimg[t] = packh(w2[kk * 64 + n], w2[(kk + 1) * 64 + n]);
    } else if (t < 13312) {       // B3H from W3 [64,256]
        int u = t - 5120;
        int j = u & 1, e = u >> 1;
        int lane = e & 31, nt = (e >> 5) & 31, s3 = e >> 10;
        int kk = 16 * s3 + 2 * (lane & 3) + (j ? 8 : 0);
        int n = 8 * nt + (lane >> 2);
        d_wimg[t] = packh(w3[kk * 256 + n], w3[(kk + 1) * 256 + n]);
    } else {                      // b2
        d_wimg[t] = __float_as_uint(b2[t - 13312]);
    }
}

// ---------------- K2: fully tensorized edge pipeline ---------------------------
__global__ void __launch_bounds__(256, 2)
k2_edge(const float* __restrict__ x, const int* __restrict__ ei,
        const float* __restrict__ ea) {
    extern __shared__ unsigned char smc[];
    int tid = threadIdx.x;
    {
        const uint4* src = (const uint4*)d_wimg;
        uint4* dst = (uint4*)smc;
        for (int i = tid; i < 3344; i += 256) dst[i] = src[i];   // 13376 u32 = 3344 uint4
    }
    __syncthreads();

    const int w = tid >> 5, lane = tid & 31;
    const int q = lane & 3, l4 = lane >> 2;
    const int bq = 2 * q;
    const float* sb2 = (const float*)(smc + SM_B2B);

    for (int tile = blockIdx.x; tile < NT256; tile += gridDim.x) {
        const int base = (tile << 8) + (w << 5) + l4;   // rows base+{0,8,16,24}
        int srcv[4], dstv[4];
        unsigned eaf[2][2];                              // L1 A fragments
#pragma unroll
        for (int r = 0; r < 4; r += 2) {
            int e0 = base + 8 * r, e1 = e0 + 8;
            srcv[r] = __ldg(&ei[e0]);     srcv[r + 1] = __ldg(&ei[e1]);
            dstv[r] = __ldg(&ei[NE + e0]); dstv[r + 1] = __ldg(&ei[NE + e1]);
            float a0 = __ldg(&ea[(size_t)e0 * 3]);
            float a1 = __ldg(&ea[(size_t)e0 * 3 + 1]);
            float a2 = __ldg(&ea[(size_t)e0 * 3 + 2]);
            float b0 = __ldg(&ea[(size_t)e1 * 3]);
            float b1v = __ldg(&ea[(size_t)e1 * 3 + 1]);
            float b2v = __ldg(&ea[(size_t)e1 * 3 + 2]);
            int m = r >> 1;
            eaf[m][0] = (q == 0) ? packh(a0, a1) : ((q == 1) ? packh(a2, 1.0f) : 0u);
            eaf[m][1] = (q == 0) ? packh(b0, b1v) : ((q == 1) ? packh(b2v, 1.0f) : 0u);
        }

        // ---- L2 (with L1 on tensor cores): C2[m][16,64] ----
        float C2[2][8][4];
#pragma unroll
        for (int m = 0; m < 2; m++)
#pragma unroll
            for (int nt = 0; nt < 8; nt++)
#pragma unroll
                for (int v = 0; v < 4; v++) C2[m][nt][v] = 0.f;

#pragma unroll
        for (int s = 0; s < 8; s++) {
            // L1: C1 = ea @ W1 + b1 (exact W1 via hi in b0-slot, lo in b1-slot)
            float C1[2][2][4];
#pragma unroll
            for (int ntl = 0; ntl < 2; ntl++)
#pragma unroll
                for (int m = 0; m < 2; m++)
#pragma unroll
                    for (int v = 0; v < 4; v++) C1[ntl][m][v] = 0.f;
#pragma unroll
            for (int ntl = 0; ntl < 2; ntl++) {
                uint2 bw = *(const uint2*)(smc + SM_B1F + (((2 * s + ntl) * 32 + lane) << 3));
#pragma unroll
                for (int m = 0; m < 2; m++) {
                    unsigned a[4] = {eaf[m][0], eaf[m][1], eaf[m][0], eaf[m][1]};
                    mma16816(C1[ntl][m], a, bw.x, bw.y);
                }
            }
            // relu + pack -> L2 A fragments (C1 layout == A fragment layout)
            unsigned Ah[2][4];
#pragma unroll
            for (int m = 0; m < 2; m++) {
                Ah[m][0] = packh(fmaxf(C1[0][m][0], 0.f), fmaxf(C1[0][m][1], 0.f));
                Ah[m][1] = packh(fmaxf(C1[0][m][2], 0.f), fmaxf(C1[0][m][3], 0.f));
                Ah[m][2] = packh(fmaxf(C1[1][m][0], 0.f), fmaxf(C1[1][m][1], 0.f));
                Ah[m][3] = packh(fmaxf(C1[1][m][2], 0.f), fmaxf(C1[1][m][3], 0.f));
            }
#pragma unroll
            for (int nt = 0; nt < 8; nt++) {
                uint2 B = *(const uint2*)(smc + SM_B2H + (((s * 8 + nt) * 32 + lane) << 3));
#pragma unroll
                for (int m = 0; m < 2; m++)
                    mma16816(C2[m][nt], Ah[m], B.x, B.y);
            }
        }

        // ---- epilogue: +b2, relu -> A3 fragments ----
        unsigned A3h[2][4][4];
#pragma unroll
        for (int m = 0; m < 2; m++)
#pragma unroll
            for (int s3 = 0; s3 < 4; s3++) {
                int c = 16 * s3 + bq;
                float2 bA = *(const float2*)&sb2[c];
                float2 bB = *(const float2*)&sb2[c + 8];
                float v00 = fmaxf(C2[m][2 * s3][0] + bA.x, 0.f);
                float v01 = fmaxf(C2[m][2 * s3][1] + bA.y, 0.f);
                float v10 = fmaxf(C2[m][2 * s3][2] + bA.x, 0.f);
                float v11 = fmaxf(C2[m][2 * s3][3] + bA.y, 0.f);
                float v20 = fmaxf(C2[m][2 * s3 + 1][0] + bB.x, 0.f);
                float v21 = fmaxf(C2[m][2 * s3 + 1][1] + bB.y, 0.f);
                float v30 = fmaxf(C2[m][2 * s3 + 1][2] + bB.x, 0.f);
                float v31 = fmaxf(C2[m][2 * s3 + 1][3] + bB.y, 0.f);
                A3h[m][s3][0] = packh(v00, v01);
                A3h[m][s3][1] = packh(v10, v11);
                A3h[m][s3][2] = packh(v20, v21);
                A3h[m][s3][3] = packh(v30, v31);
            }

        // x[src] quarters (loaded after L2 to limit register pressure)
        float4 xq[4];
#pragma unroll
        for (int r = 0; r < 4; r++)
            xq[r] = *(const float4*)&x[(size_t)srcv[r] * 16 + 4 * q];

        // ---- L3 + einsum (weight-hi only) ----
        float macc[2][2][4];
#pragma unroll
        for (int m = 0; m < 2; m++)
#pragma unroll
            for (int r2 = 0; r2 < 2; r2++)
#pragma unroll
                for (int jj = 0; jj < 4; jj++) macc[m][r2][jj] = 0.f;

#pragma unroll
        for (int grp = 0; grp < 8; grp++) {
            float C3[2][4][4];
#pragma unroll
            for (int m = 0; m < 2; m++)
#pragma unroll
                for (int t = 0; t < 4; t++)
#pragma unroll
                    for (int v = 0; v < 4; v++) C3[m][t][v] = 0.f;
#pragma unroll
            for (int s3 = 0; s3 < 4; s3++) {
#pragma unroll
                for (int t = 0; t < 4; t++) {
                    int nt = grp * 4 + t;
                    uint2 B = *(const uint2*)(smc + SM_B3H + (((s3 * 32 + nt) * 32 + lane) << 3));
#pragma unroll
                    for (int m = 0; m < 2; m++)
                        mma16816(C3[m][t], A3h[m][s3], B.x, B.y);
                }
            }
#pragma unroll
            for (int t = 0; t < 4; t++) {
                const int nt = grp * 4 + t;
                const int i = nt >> 1;
                const int sl = (lane & ~3) | (i >> 2);
                float xv[4];
#pragma unroll
                for (int r = 0; r < 4; r++) {
                    float own;
                    switch (i & 3) {
                        case 0: own = xq[r].x; break;
                        case 1: own = xq[r].y; break;
                        case 2: own = xq[r].z; break;
                        default: own = xq[r].w; break;
                    }
                    xv[r] = __shfl_sync(0xffffffffu, own, sl);
                }
                const int p = nt & 1;
#pragma unroll
                for (int m = 0; m < 2; m++) {
                    macc[m][0][2 * p]     = fmaf(C3[m][t][0], xv[2 * m], macc[m][0][2 * p]);
                    macc[m][0][2 * p + 1] = fmaf(C3[m][t][1], xv[2 * m], macc[m][0][2 * p + 1]);
                    macc[m][1][2 * p]     = fmaf(C3[m][t][2], xv[2 * m + 1], macc[m][1][2 * p]);
                    macc[m][1][2 * p + 1] = fmaf(C3[m][t][3], xv[2 * m + 1], macc[m][1][2 * p + 1]);
                }
            }
        }

        // ---- flush: + b3t[src], vector-red into d_agg[dst] ----
#pragma unroll
        for (int m = 0; m < 2; m++)
#pragma unroll
            for (int r2 = 0; r2 < 2; r2++) {
                int r = 2 * m + r2;
                float2 pA = *(const float2*)&d_b3t[(size_t)srcv[r] * 16 + bq];
                float2 pB = *(const float2*)&d_b3t[(size_t)srcv[r] * 16 + bq + 8];
                float* a = &d_agg[(size_t)dstv[r] * 16];
                redv2(a + bq,     macc[m][r2][0] + pA.x, macc[m][r2][1] + pA.y);
                redv2(a + bq + 8, macc[m][r2][2] + pB.x, macc[m][r2][3] + pB.y);
            }
    }
}

// ---------------- K3: x1 = relu(agg); xt = x1@gat_w (4 threads / node) ---------
__global__ void k3_node(const float* __restrict__ gw, const float* __restrict__ as_,
                        const float* __restrict__ ad_) {
    __shared__ float sw[256], sa[16], sbv[16];
    int tid = threadIdx.x;
    if (tid < 256) sw[tid] = gw[tid];
    if (tid < 16) { sa[tid] = as_[tid]; sbv[tid] = ad_[tid]; }
    __syncthreads();
    int gid = blockIdx.x * blockDim.x + tid;
    if (gid >= NN * 4) return;
    int n = gid >> 2, ob = (gid & 3) * 4;
    float x1[16];
#pragma unroll
    for (int i = 0; i < 16; i++) x1[i] = fmaxf(d_agg[n * 16 + i], 0.f);
    float asrc = 0.f, adst = 0.f;
    float vo[4];
#pragma unroll
    for (int oo = 0; oo < 4; oo++) {
        int o = ob + oo;
        float v = 0.f;
#pragma unroll
        for (int i = 0; i < 16; i++) v = fmaf(x1[i], sw[i * 16 + o], v);
        vo[oo] = v;
        asrc = fmaf(v, sa[o], asrc);
        adst = fmaf(v, sbv[o], adst);
    }
    *(float4*)&d_xt[(size_t)n * 16 + ob] = make_float4(vo[0], vo[1], vo[2], vo[3]);
    asrc += __shfl_xor_sync(0xffffffffu, asrc, 1);
    adst += __shfl_xor_sync(0xffffffffu, adst, 1);
    asrc += __shfl_xor_sync(0xffffffffu, asrc, 2);
    adst += __shfl_xor_sync(0xffffffffu, adst, 2);
    if ((gid & 3) == 0) {
        d_asrc[n] = asrc;
        d_adst[n] = adst;
        d_menc[n] = enc_f(lrelu(asrc + adst));   // self-loop seeds the max
    }
}

// ---------------- K4: edge logits + segment max (2 edges / thread) -------------
__global__ void k4_edge(const int* __restrict__ ei) {
    int t = blockIdx.x * blockDim.x + threadIdx.x;
    if (t >= NE / 2) return;
    int2 s2 = __ldg(&((const int2*)ei)[t]);
    int2 d2 = __ldg(&((const int2*)(ei + NE))[t]);
    float v0 = lrelu(d_asrc[s2.x] + d_adst[d2.x]);
    float v1 = lrelu(d_asrc[s2.y] + d_adst[d2.y]);
    *(float2*)&d_ebuf[2 * t] = make_float2(v0, v1);
    atomicMax(&d_menc[d2.x], enc_f(v0));
    atomicMax(&d_menc[d2.y], enc_f(v1));
}

// ---------------- K6: softmax scatter (2 edges / thread-part, red.v4) ----------
__global__ void k6_edge(const int* __restrict__ ei) {
    int gid = blockIdx.x * blockDim.x + threadIdx.x;
    if (gid >= NE * 2) return;
    int pe = gid >> 2;        // edge-pair index (edges 2pe, 2pe+1)
    int part = gid & 3;
    int2 s2 = __ldg(&((const int2*)ei)[pe]);
    int2 d2 = __ldg(&((const int2*)(ei + NE))[pe]);
    float2 e2 = __ldg(&((const float2*)d_ebuf)[pe]);
    float w0 = __expf(e2.x - dec_f(d_menc[d2.x]));
    float w1 = __expf(e2.y - dec_f(d_menc[d2.y]));
    float4 x0 = *(const float4*)&d_xt[(size_t)s2.x * 16 + part * 4];
    float4 x1 = *(const float4*)&d_xt[(size_t)s2.y * 16 + part * 4];
    redv4(&d_gout[(size_t)d2.x * 16 + part * 4],
          w0 * x0.x, w0 * x0.y, w0 * x0.z, w0 * x0.w);
    redv4(&d_gout[(size_t)d2.y * 16 + part * 4],
          w1 * x1.x, w1 * x1.y, w1 * x1.z, w1 * x1.w);
    if (part == 0) {
        atomicAdd(&d_z[d2.x], w0);
        atomicAdd(&d_z[d2.y], w1);
    }
}

// ---------------- K7: quad-cooperative normalize + fc1 (4 thr / node) ----------
__global__ void k7_node(const float* __restrict__ fw, const float* __restrict__ fb,
                        const float* __restrict__ gb, float* __restrict__ out) {
    __shared__ float sw[1024], sbv[64], sgb[16];
    int tid = threadIdx.x;
    for (int i = tid; i < 1024; i += blockDim.x) sw[i] = fw[i];
    if (tid < 64) sbv[tid] = fb[tid];
    if (tid < 16) sgb[tid] = gb[tid];
    __syncthreads();
    int gid = blockIdx.x * blockDim.x + tid;
    if (gid >= NN * 4) return;
    int n = gid >> 2, qk = gid & 3, ob = qk * 4, jb = qk * 16;
    int lane = tid & 31;
    float m = dec_f(d_menc[n]);
    float wself = __expf(lrelu(d_asrc[n] + d_adst[n]) - m);
    float inv = 1.f / (d_z[n] + wself);
    // each thread computes its 4 x2 values from one float4 of gout/xt
    float4 g4 = *(const float4*)&d_gout[(size_t)n * 16 + ob];
    float4 t4 = *(const float4*)&d_xt[(size_t)n * 16 + ob];
    float x2q[4];
    x2q[0] = fmaxf(fmaf(wself, t4.x, g4.x) * inv + sgb[ob],     0.f);
    x2q[1] = fmaxf(fmaf(wself, t4.y, g4.y) * inv + sgb[ob + 1], 0.f);
    x2q[2] = fmaxf(fmaf(wself, t4.z, g4.z) * inv + sgb[ob + 2], 0.f);
    x2q[3] = fmaxf(fmaf(wself, t4.w, g4.w) * inv + sgb[ob + 3], 0.f);
    // gather all 16 x2 via quad shfl (grid is quad-aligned: NN*4 = 200000)
    float x2[16];
#pragma unroll
    for (int i = 0; i < 16; i++)
        x2[i] = __shfl_sync(0xffffffffu, x2q[i & 3], (lane & ~3) | (i >> 2));
#pragma unroll 4
    for (int jj = 0; jj < 16; jj++) {
        int j = jb + jj;
        float a = sbv[j];
#pragma unroll
        for (int i = 0; i < 16; i++) a = fmaf(x2[i], sw[i * 64 + j], a);
        out[(size_t)n * 64 + j] = fmaxf(a, 0.f);
    }
}

// ---------------- launch -------------------------------------------------------
extern "C" void kernel_launch(void* const* d_in, const int* in_sizes, int n_in,
                              void* d_out, int out_size) {
    const float* x = (const float*)d_in[0];
    const int* ei = (const int*)d_in[1];
    const float* ea = (const float*)d_in[2];
    const float* w1 = (const float*)d_in[4];
    const float* b1 = (const float*)d_in[5];
    const float* w2 = (const float*)d_in[6];
    const float* b2 = (const float*)d_in[7];
    const float* w3 = (const float*)d_in[8];
    const float* b3 = (const float*)d_in[9];
    const float* rootw = (const float*)d_in[10];
    const float* nnb = (const float*)d_in[11];
    const float* gatw = (const float*)d_in[12];
    const float* atts = (const float*)d_in[13];
    const float* attd = (const float*)d_in[14];
    const float* gatb = (const float*)d_in[15];
    const float* fc1w = (const float*)d_in[16];
    const float* fc1b = (const float*)d_in[17];
    float* out = (float*)d_out;

    cudaFuncSetAttribute(k2_edge, cudaFuncAttributeMaxDynamicSharedMemorySize, K2_SMEM);

    k0_fused<<<NB_K0 + NB_K1, 256>>>(x, rootw, nnb, b3, w1, b1, w2, w3, b2);
    k2_edge<<<296, 256, K2_SMEM>>>(x, ei, ea);
    k3_node<<<(NN * 4 + 255) / 256, 256>>>(gatw, atts, attd);
    k4_edge<<<(NE / 2 + 255) / 256, 256>>>(ei);
    k6_edge<<<(NE * 2 + 255) / 256, 256>>>(ei);
    k7_node<<<(NN * 4 + 255) / 256, 256>>>(fc1w, fc1b, gatb, out);
}

// round 16
// speedup vs baseline: 1.0549x; 1.0026x over previous
#include <cuda_runtime.h>
#include <cuda_fp16.h>
#include <cstdint>

#define NN 50000
#define NE 800000
#define NT256 3125            // 256-edge tiles
#define NB_K0 782             // ceil(NN*4/256)
#define NB_K1 53              // ceil(13376/256)

// ---------------- device scratch ----------------------------------------------
__device__ float d_agg[NN * 16];
__device__ float d_b3t[NN * 16];
__device__ float d_xt[NN * 16];
__device__ float d_asrc[NN];
__device__ float d_adst[NN];
__device__ unsigned int d_menc[NN];
__device__ float d_z[NN];
__device__ float d_gout[NN * 16];
__device__ float d_ebuf[NE];
// packed weight images (compact, conflict-free):
// B1F (1024 u32: {hi,lo} uint2/lane) | B2H (4096) | B3H (8192) | b2 (64)
__device__ unsigned d_wimg[13376];

// ---------------- helpers ------------------------------------------------------
__device__ __forceinline__ unsigned enc_f(float f) {
    unsigned u = __float_as_uint(f);
    return (u & 0x80000000u) ? ~u : (u | 0x80000000u);
}
__device__ __forceinline__ float dec_f(unsigned k) {
    return __uint_as_float((k & 0x80000000u) ? (k & 0x7fffffffu) : ~k);
}
__device__ __forceinline__ float lrelu(float v) { return v > 0.f ? v : 0.2f * v; }

__device__ __forceinline__ unsigned packh(float a, float b) {
    unsigned r;
    asm("cvt.rn.f16x2.f32 %0, %1, %2;" : "=r"(r) : "f"(b), "f"(a));
    return r;
}
__device__ __forceinline__ unsigned loh(unsigned hi, float a, float b) {
    float ha = __half2float(__ushort_as_half((unsigned short)(hi & 0xFFFFu)));
    float hb = __half2float(__ushort_as_half((unsigned short)(hi >> 16)));
    return packh(a - ha, b - hb);
}

__device__ __forceinline__ void mma16816(float* c, const unsigned* a,
                                         unsigned b0, unsigned b1) {
    asm volatile(
        "mma.sync.aligned.m16n8k16.row.col.f32.f16.f16.f32 "
        "{%0,%1,%2,%3}, {%4,%5,%6,%7}, {%8,%9}, {%0,%1,%2,%3};"
        : "+f"(c[0]), "+f"(c[1]), "+f"(c[2]), "+f"(c[3])
        : "r"(a[0]), "r"(a[1]), "r"(a[2]), "r"(a[3]), "r"(b0), "r"(b1));
}

// vector global reductions (sm_90+ baseline)
__device__ __forceinline__ void redv2(float* p, float a, float b) {
    asm volatile("red.global.add.v2.f32 [%0], {%1, %2};"
                 :: "l"(p), "f"(a), "f"(b) : "memory");
}
__device__ __forceinline__ void redv4(float* p, float a, float b, float c, float d) {
    asm volatile("red.global.add.v4.f32 [%0], {%1, %2, %3, %4};"
                 :: "l"(p), "f"(a), "f"(b), "f"(c), "f"(d) : "memory");
}

// smem byte offsets inside k2 (all 8B-aligned; lane stride 8B -> conflict-free)
#define SM_B1F 0
#define SM_B2H 4096
#define SM_B3H 20480
#define SM_B2B 53248
#define K2_SMEM 53504

// ---------------- K0: fused prep — node init (blocks < NB_K0) + weight pack ----
__global__ void k0_fused(const float* __restrict__ x, const float* __restrict__ rw,
                         const float* __restrict__ nb, const float* __restrict__ b3,
                         const float* __restrict__ w1, const float* __restrict__ b1,
                         const float* __restrict__ w2, const float* __restrict__ w3,
                         const float* __restrict__ b2) {
    if (blockIdx.x < NB_K0) {
        int gid = blockIdx.x * blockDim.x + threadIdx.x;
        if (gid >= NN * 4) return;
        int n = gid >> 2, qk = gid & 3, ob = qk * 4;
        int lane = threadIdx.x & 31;
        // quad-cooperative x load: each thread loads its float4, shfl-gather 16
        float4 xv = __ldg((const float4*)&x[(size_t)n * 16 + ob]);
        float xq[4] = {xv.x, xv.y, xv.z, xv.w};
        float xr[16];
#pragma unroll
        for (int i = 0; i < 16; i++)
            xr[i] = __shfl_sync(0xffffffffu, xq[i & 3], (lane & ~3) | (i >> 2));
        float av[4], bv[4];
#pragma unroll
        for (int oo = 0; oo < 4; oo++) {
            int o = ob + oo;
            float a = __ldg(&nb[o]);
            float b = 0.f;
#pragma unroll
            for (int i = 0; i < 16; i++) {
                a = fmaf(xr[i], __ldg(&rw[i * 16 + o]), a);
                b = fmaf(xr[i], __ldg(&b3[i * 16 + o]), b);
            }
            av[oo] = a; bv[oo] = b;
        }
        *(float4*)&d_agg[(size_t)n * 16 + ob] = make_float4(av[0], av[1], av[2], av[3]);
        *(float4*)&d_b3t[(size_t)n * 16 + ob] = make_float4(bv[0], bv[1], bv[2], bv[3]);
        *(float4*)&d_gout[(size_t)n * 16 + ob] = make_float4(0.f, 0.f, 0.f, 0.f);
        if (qk == 0) d_z[n] = 0.f;
        return;
    }
    // ---- weight pack path ----
    int t = (blockIdx.x - NB_K0) * blockDim.x + threadIdx.x;
    if (t >= 13376) return;
    if (t < 1024) {               // B1F
        int j = t & 1, e = t >> 1;
        int lane = e & 31, nt = e >> 5;
        int q = lane & 3, n = 8 * nt + (lane >> 2);
        float va = 0.f, vb = 0.f;
        if (q == 0) { va = w1[n]; vb = w1[128 + n]; }
        else if (q == 1) { va = w1[256 + n]; vb = b1[n]; }
        unsigned hi = packh(va, vb);
        d_wimg[t] = (q < 2) ? ((j == 0) ? hi : loh(hi, va, vb)) : 0u;
    } else if (t < 5120) {        // B2H from W2 [128,64]
        int u = t - 1024;
        int j = u & 1, e = u >> 1;
        int lane = e & 31, nt = (e >> 5) & 7, s = e >> 8;
        int kk = 16 * s + 2 * (lane & 3) + (j ? 8 : 0);
        int n = 8 * nt + (lane >> 2);
        d_wimg[t] = packh(w2[kk * 64 + n], w2[(kk + 1) * 64 + n]);
    } else if (t < 13312) {       // B3H from W3 [64,256]
        int u = t - 5120;
        int j = u & 1, e = u >> 1;
        int lane = e & 31, nt = (e >> 5) & 31, s3 = e >> 10;
        int kk = 16 * s3 + 2 * (lane & 3) + (j ? 8 : 0);
        int n = 8 * nt + (lane >> 2);
        d_wimg[t] = packh(w3[kk * 256 + n], w3[(kk + 1) * 256 + n]);
    } else {                      // b2
        d_wimg[t] = __float_as_uint(b2[t - 13312]);
    }
}

// ---------------- K2: fully tensorized edge pipeline ---------------------------
__global__ void __launch_bounds__(256, 2)
k2_edge(const float* __restrict__ x, const int* __restrict__ ei,
        const float* __restrict__ ea) {
    extern __shared__ unsigned char smc[];
    int tid = threadIdx.x;
    {
        const uint4* src = (const uint4*)d_wimg;
        uint4* dst = (uint4*)smc;
        for (int i = tid; i < 3344; i += 256) dst[i] = src[i];   // 13376 u32 = 3344 uint4
    }
    __syncthreads();

    const int w = tid >> 5, lane = tid & 31;
    const int q = lane & 3, l4 = lane >> 2;
    const int bq = 2 * q;
    const float* sb2 = (const float*)(smc + SM_B2B);

    for (int tile = blockIdx.x; tile < NT256; tile += gridDim.x) {
        const int base = (tile << 8) + (w << 5) + l4;   // rows base+{0,8,16,24}
        int srcv[4], dstv[4];
        unsigned eaf[2][2];                              // L1 A fragments
#pragma unroll
        for (int r = 0; r < 4; r += 2) {
            int e0 = base + 8 * r, e1 = e0 + 8;
            srcv[r] = __ldg(&ei[e0]);     srcv[r + 1] = __ldg(&ei[e1]);
            dstv[r] = __ldg(&ei[NE + e0]); dstv[r + 1] = __ldg(&ei[NE + e1]);
            float a0 = __ldg(&ea[(size_t)e0 * 3]);
            float a1 = __ldg(&ea[(size_t)e0 * 3 + 1]);
            float a2 = __ldg(&ea[(size_t)e0 * 3 + 2]);
            float b0 = __ldg(&ea[(size_t)e1 * 3]);
            float b1v = __ldg(&ea[(size_t)e1 * 3 + 1]);
            float b2v = __ldg(&ea[(size_t)e1 * 3 + 2]);
            int m = r >> 1;
            eaf[m][0] = (q == 0) ? packh(a0, a1) : ((q == 1) ? packh(a2, 1.0f) : 0u);
            eaf[m][1] = (q == 0) ? packh(b0, b1v) : ((q == 1) ? packh(b2v, 1.0f) : 0u);
        }

        // ---- L2 (with L1 on tensor cores): C2[m][16,64] ----
        float C2[2][8][4];
#pragma unroll
        for (int m = 0; m < 2; m++)
#pragma unroll
            for (int nt = 0; nt < 8; nt++)
#pragma unroll
                for (int v = 0; v < 4; v++) C2[m][nt][v] = 0.f;

#pragma unroll
        for (int s = 0; s < 8; s++) {
            // L1: C1 = ea @ W1 + b1 (exact W1 via hi in b0-slot, lo in b1-slot)
            float C1[2][2][4];
#pragma unroll
            for (int ntl = 0; ntl < 2; ntl++)
#pragma unroll
                for (int m = 0; m < 2; m++)
#pragma unroll
                    for (int v = 0; v < 4; v++) C1[ntl][m][v] = 0.f;
#pragma unroll
            for (int ntl = 0; ntl < 2; ntl++) {
                uint2 bw = *(const uint2*)(smc + SM_B1F + (((2 * s + ntl) * 32 + lane) << 3));
#pragma unroll
                for (int m = 0; m < 2; m++) {
                    unsigned a[4] = {eaf[m][0], eaf[m][1], eaf[m][0], eaf[m][1]};
                    mma16816(C1[ntl][m], a, bw.x, bw.y);
                }
            }
            // relu + pack -> L2 A fragments (C1 layout == A fragment layout)
            unsigned Ah[2][4];
#pragma unroll
            for (int m = 0; m < 2; m++) {
                Ah[m][0] = packh(fmaxf(C1[0][m][0], 0.f), fmaxf(C1[0][m][1], 0.f));
                Ah[m][1] = packh(fmaxf(C1[0][m][2], 0.f), fmaxf(C1[0][m][3], 0.f));
                Ah[m][2] = packh(fmaxf(C1[1][m][0], 0.f), fmaxf(C1[1][m][1], 0.f));
                Ah[m][3] = packh(fmaxf(C1[1][m][2], 0.f), fmaxf(C1[1][m][3], 0.f));
            }
#pragma unroll
            for (int nt = 0; nt < 8; nt++) {
                uint2 B = *(const uint2*)(smc + SM_B2H + (((s * 8 + nt) * 32 + lane) << 3));
#pragma unroll
                for (int m = 0; m < 2; m++)
                    mma16816(C2[m][nt], Ah[m], B.x, B.y);
            }
        }

        // ---- epilogue: +b2, relu -> A3 fragments ----
        unsigned A3h[2][4][4];
#pragma unroll
        for (int m = 0; m < 2; m++)
#pragma unroll
            for (int s3 = 0; s3 < 4; s3++) {
                int c = 16 * s3 + bq;
                float2 bA = *(const float2*)&sb2[c];
                float2 bB = *(const float2*)&sb2[c + 8];
                float v00 = fmaxf(C2[m][2 * s3][0] + bA.x, 0.f);
                float v01 = fmaxf(C2[m][2 * s3][1] + bA.y, 0.f);
                float v10 = fmaxf(C2[m][2 * s3][2] + bA.x, 0.f);
                float v11 = fmaxf(C2[m][2 * s3][3] + bA.y, 0.f);
                float v20 = fmaxf(C2[m][2 * s3 + 1][0] + bB.x, 0.f);
                float v21 = fmaxf(C2[m][2 * s3 + 1][1] + bB.y, 0.f);
                float v30 = fmaxf(C2[m][2 * s3 + 1][2] + bB.x, 0.f);
                float v31 = fmaxf(C2[m][2 * s3 + 1][3] + bB.y, 0.f);
                A3h[m][s3][0] = packh(v00, v01);
                A3h[m][s3][1] = packh(v10, v11);
                A3h[m][s3][2] = packh(v20, v21);
                A3h[m][s3][3] = packh(v30, v31);
            }

        // x[src] quarters (loaded after L2 to limit register pressure)
        float4 xq[4];
#pragma unroll
        for (int r = 0; r < 4; r++)
            xq[r] = *(const float4*)&x[(size_t)srcv[r] * 16 + 4 * q];

        // ---- L3 + einsum (weight-hi only) ----
        float macc[2][2][4];
#pragma unroll
        for (int m = 0; m < 2; m++)
#pragma unroll
            for (int r2 = 0; r2 < 2; r2++)
#pragma unroll
                for (int jj = 0; jj < 4; jj++) macc[m][r2][jj] = 0.f;

#pragma unroll
        for (int grp = 0; grp < 8; grp++) {
            float C3[2][4][4];
#pragma unroll
            for (int m = 0; m < 2; m++)
#pragma unroll
                for (int t = 0; t < 4; t++)
#pragma unroll
                    for (int v = 0; v < 4; v++) C3[m][t][v] = 0.f;
#pragma unroll
            for (int s3 = 0; s3 < 4; s3++) {
#pragma unroll
                for (int t = 0; t < 4; t++) {
                    int nt = grp * 4 + t;
                    uint2 B = *(const uint2*)(smc + SM_B3H + (((s3 * 32 + nt) * 32 + lane) << 3));
#pragma unroll
                    for (int m = 0; m < 2; m++)
                        mma16816(C3[m][t], A3h[m][s3], B.x, B.y);
                }
            }
#pragma unroll
            for (int t = 0; t < 4; t++) {
                const int nt = grp * 4 + t;
                const int i = nt >> 1;
                const int sl = (lane & ~3) | (i >> 2);
                float xv[4];
#pragma unroll
                for (int r = 0; r < 4; r++) {
                    float own;
                    switch (i & 3) {
                        case 0: own = xq[r].x; break;
                        case 1: own = xq[r].y; break;
                        case 2: own = xq[r].z; break;
                        default: own = xq[r].w; break;
                    }
                    xv[r] = __shfl_sync(0xffffffffu, own, sl);
                }
                const int p = nt & 1;
#pragma unroll
                for (int m = 0; m < 2; m++) {
                    macc[m][0][2 * p]     = fmaf(C3[m][t][0], xv[2 * m], macc[m][0][2 * p]);
                    macc[m][0][2 * p + 1] = fmaf(C3[m][t][1], xv[2 * m], macc[m][0][2 * p + 1]);
                    macc[m][1][2 * p]     = fmaf(C3[m][t][2], xv[2 * m + 1], macc[m][1][2 * p]);
                    macc[m][1][2 * p + 1] = fmaf(C3[m][t][3], xv[2 * m + 1], macc[m][1][2 * p + 1]);
                }
            }
        }

        // ---- flush: + b3t[src], vector-red into d_agg[dst] ----
#pragma unroll
        for (int m = 0; m < 2; m++)
#pragma unroll
            for (int r2 = 0; r2 < 2; r2++) {
                int r = 2 * m + r2;
                float2 pA = *(const float2*)&d_b3t[(size_t)srcv[r] * 16 + bq];
                float2 pB = *(const float2*)&d_b3t[(size_t)srcv[r] * 16 + bq + 8];
                float* a = &d_agg[(size_t)dstv[r] * 16];
                redv2(a + bq,     macc[m][r2][0] + pA.x, macc[m][r2][1] + pA.y);
                redv2(a + bq + 8, macc[m][r2][2] + pB.x, macc[m][r2][3] + pB.y);
            }
    }
}

// ---------------- K3: x1 = relu(agg); xt = x1@gat_w (4 thr / node, quad-shfl) --
__global__ void k3_node(const float* __restrict__ gw, const float* __restrict__ as_,
                        const float* __restrict__ ad_) {
    __shared__ float sw[256], sa[16], sbv[16];
    int tid = threadIdx.x;
    if (tid < 256) sw[tid] = gw[tid];
    if (tid < 16) { sa[tid] = as_[tid]; sbv[tid] = ad_[tid]; }
    __syncthreads();
    int gid = blockIdx.x * blockDim.x + tid;
    if (gid >= NN * 4) return;
    int n = gid >> 2, qk = gid & 3, ob = qk * 4;
    int lane = tid & 31;
    // quad-cooperative agg load
    float4 g4 = *(const float4*)&d_agg[(size_t)n * 16 + ob];
    float x1q[4] = {fmaxf(g4.x, 0.f), fmaxf(g4.y, 0.f),
                    fmaxf(g4.z, 0.f), fmaxf(g4.w, 0.f)};
    float x1[16];
#pragma unroll
    for (int i = 0; i < 16; i++)
        x1[i] = __shfl_sync(0xffffffffu, x1q[i & 3], (lane & ~3) | (i >> 2));
    float asrc = 0.f, adst = 0.f;
    float vo[4];
#pragma unroll
    for (int oo = 0; oo < 4; oo++) {
        int o = ob + oo;
        float v = 0.f;
#pragma unroll
        for (int i = 0; i < 16; i++) v = fmaf(x1[i], sw[i * 16 + o], v);
        vo[oo] = v;
        asrc = fmaf(v, sa[o], asrc);
        adst = fmaf(v, sbv[o], adst);
    }
    *(float4*)&d_xt[(size_t)n * 16 + ob] = make_float4(vo[0], vo[1], vo[2], vo[3]);
    asrc += __shfl_xor_sync(0xffffffffu, asrc, 1);
    adst += __shfl_xor_sync(0xffffffffu, adst, 1);
    asrc += __shfl_xor_sync(0xffffffffu, asrc, 2);
    adst += __shfl_xor_sync(0xffffffffu, adst, 2);
    if (qk == 0) {
        d_asrc[n] = asrc;
        d_adst[n] = adst;
        d_menc[n] = enc_f(lrelu(asrc + adst));   // self-loop seeds the max
    }
}

// ---------------- K4: edge logits + segment max (4 edges / thread, high MLP) ---
__global__ void k4_edge(const int* __restrict__ ei) {
    int t = blockIdx.x * blockDim.x + threadIdx.x;
    if (t >= NE / 4) return;
    int4 s4 = __ldg(&((const int4*)ei)[t]);
    int4 d4 = __ldg(&((const int4*)(ei + NE))[t]);
    // issue all 8 scattered loads up front (MLP=8 overlaps latency)
    float as0 = d_asrc[s4.x], as1 = d_asrc[s4.y];
    float as2 = d_asrc[s4.z], as3 = d_asrc[s4.w];
    float ad0 = d_adst[d4.x], ad1 = d_adst[d4.y];
    float ad2 = d_adst[d4.z], ad3 = d_adst[d4.w];
    float v0 = lrelu(as0 + ad0);
    float v1 = lrelu(as1 + ad1);
    float v2 = lrelu(as2 + ad2);
    float v3 = lrelu(as3 + ad3);
    *(float4*)&d_ebuf[4 * t] = make_float4(v0, v1, v2, v3);
    atomicMax(&d_menc[d4.x], enc_f(v0));
    atomicMax(&d_menc[d4.y], enc_f(v1));
    atomicMax(&d_menc[d4.z], enc_f(v2));
    atomicMax(&d_menc[d4.w], enc_f(v3));
}

// ---------------- K6: softmax scatter (2 edges / thread-part, red.v4) ----------
__global__ void k6_edge(const int* __restrict__ ei) {
    int gid = blockIdx.x * blockDim.x + threadIdx.x;
    if (gid >= NE * 2) return;
    int pe = gid >> 2;        // edge-pair index (edges 2pe, 2pe+1)
    int part = gid & 3;
    int2 s2 = __ldg(&((const int2*)ei)[pe]);
    int2 d2 = __ldg(&((const int2*)(ei + NE))[pe]);
    float2 e2 = __ldg(&((const float2*)d_ebuf)[pe]);
    float w0 = __expf(e2.x - dec_f(d_menc[d2.x]));
    float w1 = __expf(e2.y - dec_f(d_menc[d2.y]));
    float4 x0 = *(const float4*)&d_xt[(size_t)s2.x * 16 + part * 4];
    float4 x1 = *(const float4*)&d_xt[(size_t)s2.y * 16 + part * 4];
    redv4(&d_gout[(size_t)d2.x * 16 + part * 4],
          w0 * x0.x, w0 * x0.y, w0 * x0.z, w0 * x0.w);
    redv4(&d_gout[(size_t)d2.y * 16 + part * 4],
          w1 * x1.x, w1 * x1.y, w1 * x1.z, w1 * x1.w);
    if (part == 0) {
        atomicAdd(&d_z[d2.x], w0);
        atomicAdd(&d_z[d2.y], w1);
    }
}

// ---------------- K7: quad-cooperative normalize + fc1 (4 thr / node) ----------
__global__ void k7_node(const float* __restrict__ fw, const float* __restrict__ fb,
                        const float* __restrict__ gb, float* __restrict__ out) {
    __shared__ float sw[1024], sbv[64], sgb[16];
    int tid = threadIdx.x;
    for (int i = tid; i < 1024; i += blockDim.x) sw[i] = fw[i];
    if (tid < 64) sbv[tid] = fb[tid];
    if (tid < 16) sgb[tid] = gb[tid];
    __syncthreads();
    int gid = blockIdx.x * blockDim.x + tid;
    if (gid >= NN * 4) return;
    int n = gid >> 2, qk = gid & 3, ob = qk * 4, jb = qk * 16;
    int lane = tid & 31;
    float m = dec_f(d_menc[n]);
    float wself = __expf(lrelu(d_asrc[n] + d_adst[n]) - m);
    float inv = 1.f / (d_z[n] + wself);
    float4 g4 = *(const float4*)&d_gout[(size_t)n * 16 + ob];
    float4 t4 = *(const float4*)&d_xt[(size_t)n * 16 + ob];
    float x2q[4];
    x2q[0] = fmaxf(fmaf(wself, t4.x, g4.x) * inv + sgb[ob],     0.f);
    x2q[1] = fmaxf(fmaf(wself, t4.y, g4.y) * inv + sgb[ob + 1], 0.f);
    x2q[2] = fmaxf(fmaf(wself, t4.z, g4.z) * inv + sgb[ob + 2], 0.f);
    x2q[3] = fmaxf(fmaf(wself, t4.w, g4.w) * inv + sgb[ob + 3], 0.f);
    float x2[16];
#pragma unroll
    for (int i = 0; i < 16; i++)
        x2[i] = __shfl_sync(0xffffffffu, x2q[i & 3], (lane & ~3) | (i >> 2));
#pragma unroll 4
    for (int jj = 0; jj < 16; jj++) {
        int j = jb + jj;
        float a = sbv[j];
#pragma unroll
        for (int i = 0; i < 16; i++) a = fmaf(x2[i], sw[i * 64 + j], a);
        out[(size_t)n * 64 + j] = fmaxf(a, 0.f);
    }
}

// ---------------- launch -------------------------------------------------------
extern "C" void kernel_launch(void* const* d_in, const int* in_sizes, int n_in,
                              void* d_out, int out_size) {
    const float* x = (const float*)d_in[0];
    const int* ei = (const int*)d_in[1];
    const float* ea = (const float*)d_in[2];
    const float* w1 = (const float*)d_in[4];
    const float* b1 = (const float*)d_in[5];
    const float* w2 = (const float*)d_in[6];
    const float* b2 = (const float*)d_in[7];
    const float* w3 = (const float*)d_in[8];
    const float* b3 = (const float*)d_in[9];
    const float* rootw = (const float*)d_in[10];
    const float* nnb = (const float*)d_in[11];
    const float* gatw = (const float*)d_in[12];
    const float* atts = (const float*)d_in[13];
    const float* attd = (const float*)d_in[14];
    const float* gatb = (const float*)d_in[15];
    const float* fc1w = (const float*)d_in[16];
    const float* fc1b = (const float*)d_in[17];
    float* out = (float*)d_out;

    cudaFuncSetAttribute(k2_edge, cudaFuncAttributeMaxDynamicSharedMemorySize, K2_SMEM);

    k0_fused<<<NB_K0 + NB_K1, 256>>>(x, rootw, nnb, b3, w1, b1, w2, w3, b2);
    k2_edge<<<296, 256, K2_SMEM>>>(x, ei, ea);
    k3_node<<<(NN * 4 + 255) / 256, 256>>>(gatw, atts, attd);
    k4_edge<<<(NE / 4 + 255) / 256, 256>>>(ei);
    k6_edge<<<(NE * 2 + 255) / 256, 256>>>(ei);
    k7_node<<<(NN * 4 + 255) / 256, 256>>>(fc1w, fc1b, gatb, out);
}